// round 8
// baseline (speedup 1.0000x reference)
#include <cuda_runtime.h>
#include <math.h>

#define MAXN 131072
#define DIM  512
#define HALO 64

// Scratch (no allocations allowed in kernel_launch)
__device__ float g_dot[MAXN];     // f_j . attn_w
__device__ float g_scores[MAXN];  // windowed-mean scores
__device__ float g_gw[MAXN];      // g_j = sum_{i in win(j)} w_i / c_i
__device__ float g_pm[2048];      // per-block partial max
__device__ float g_ps[2048];      // per-block partial sumexp

// ---------------- K1: per-row dot product, one warp per row ----------------
__global__ void k_dot(const float* __restrict__ f, const float* __restrict__ w, int n) {
    int warp = threadIdx.x >> 5;
    int lane = threadIdx.x & 31;
    int row  = blockIdx.x * (blockDim.x >> 5) + warp;
    if (row >= n) return;
    const float4* fr = (const float4*)f + (size_t)row * (DIM / 4);
    const float4* wv = (const float4*)w;
    float s = 0.f;
#pragma unroll
    for (int i = 0; i < DIM / 128; i++) {
        float4 a = __ldcs(&fr[lane + 32 * i]);   // streaming: read-once data
        float4 b = __ldg(&wv[lane + 32 * i]);    // hot: keep in L1
        s += a.x * b.x + a.y * b.y + a.z * b.z + a.w * b.w;
    }
#pragma unroll
    for (int o = 16; o; o >>= 1) s += __shfl_down_sync(0xffffffffu, s, o);
    if (lane == 0) g_dot[row] = s;
}

// ------- K2: windowed-mean scores (shared tile) + per-block softmax partials -------
__global__ void k_scores(int n, const int* __restrict__ kptr, const float* __restrict__ bptr) {
    __shared__ float sh_d[256 + 2 * HALO];
    int t = threadIdx.x;
    int lane = t & 31, warp = t >> 5;
    int base = blockIdx.x * 256;
    for (int idx = t; idx < 256 + 2 * HALO; idx += 256) {
        int p = min(max(base - HALO + idx, 0), n - 1);
        sh_d[idx] = g_dot[p];
    }
    __syncthreads();
    int i = base + t;
    int k = *kptr;
    float val = -3.0e38f;
    if (i < n) {
        int lo = max(i - k, 0);
        int hi = min(i + k, n - 1);
        float s = 0.f;
        if (k <= HALO) {
            for (int j = lo; j <= hi; j++) s += sh_d[j - base + HALO];
        } else {
            for (int j = lo; j <= hi; j++) s += g_dot[j];
        }
        val = s / (float)(hi - lo + 1) + bptr[0];
        g_scores[i] = val;
    }
    float m = val;
#pragma unroll
    for (int o = 16; o; o >>= 1) m = fmaxf(m, __shfl_xor_sync(0xffffffffu, m, o));
    __shared__ float wm[8];
    if (lane == 0) wm[warp] = m;
    __syncthreads();
    float bmax = wm[0];
#pragma unroll
    for (int q = 1; q < 8; q++) bmax = fmaxf(bmax, wm[q]);
    float e = (i < n) ? __expf(val - bmax) : 0.f;
#pragma unroll
    for (int o = 16; o; o >>= 1) e += __shfl_xor_sync(0xffffffffu, e, o);
    __shared__ float ws[8];
    if (lane == 0) ws[warp] = e;
    __syncthreads();
    if (t == 0) {
        float s = ws[0];
#pragma unroll
        for (int q = 1; q < 8; q++) s += ws[q];
        g_pm[blockIdx.x] = bmax;
        g_ps[blockIdx.x] = s;
    }
}

// --- K3: (fused) per-block redundant softmax merge + w_i out + g_j + zero bag ---
__global__ void k_weights(float* __restrict__ out, int n, const int* __restrict__ kptr, int nb) {
    __shared__ float sm[256];
    __shared__ float ssum[256];
    __shared__ float sh_e[256 + 2 * HALO];
    int t = threadIdx.x;
    float m = -3.0e38f, s = 0.f;
    for (int p = t; p < nb; p += 256) {
        float mi = g_pm[p], si = g_ps[p];
        float nm = fmaxf(m, mi);
        s = s * __expf(m - nm) + si * __expf(mi - nm);
        m = nm;
    }
    sm[t] = m; ssum[t] = s;
    __syncthreads();
    for (int o = 128; o; o >>= 1) {
        if (t < o) {
            float m2 = sm[t + o], s2 = ssum[t + o];
            float nm = fmaxf(sm[t], m2);
            ssum[t] = ssum[t] * __expf(sm[t] - nm) + s2 * __expf(m2 - nm);
            sm[t] = nm;
        }
        __syncthreads();
    }
    float M = sm[0];
    float invS = 1.f / ssum[0];
    int base = blockIdx.x * 256;
    for (int idx = t; idx < 256 + 2 * HALO; idx += 256) {
        int p = min(max(base - HALO + idx, 0), n - 1);
        sh_e[idx] = __expf(g_scores[p] - M);
    }
    __syncthreads();
    int i = base + t;
    if (i < DIM) out[i] = 0.f;   // zero full bag region (blocks 0+1 cover 512)
    if (i >= n) return;
    int k = *kptr;
    float wi = sh_e[t + HALO] * invS;
    out[DIM + i] = wi;
    int lo = max(i - k, 0);
    int hi = min(i + k, n - 1);
    float g = 0.f;
    if (k <= HALO) {
        for (int j = lo; j <= hi; j++) {
            int loj = max(j - k, 0);
            int hij = min(j + k, n - 1);
            g += sh_e[j - base + HALO] / (float)(hij - loj + 1);
        }
    } else {
        for (int j = lo; j <= hi; j++) {
            int loj = max(j - k, 0);
            int hij = min(j + k, n - 1);
            g += __expf(g_scores[j] - M) / (float)(hij - loj + 1);
        }
    }
    g_gw[i] = g * invS;
}

// ---------------- K4: bag[c] = sum_j g_j * f[j][c]  (vectorized) ----------------
// 512 threads: q = tid&127 -> column group (4 cols via float4), r = tid>>7 -> row phase.
// Per iteration: one LDG.128 of features + one warp-uniform g_gw load.
__global__ void k_bag(const float* __restrict__ f, float* __restrict__ out, int n) {
    int tid = threadIdx.x;
    int q = tid & 127;
    int r = tid >> 7;                         // 0..3
    int nb = gridDim.x;
    int chunk = (n + nb - 1) / nb;
    int j0 = blockIdx.x * chunk;
    int j1 = min(j0 + chunk, n);
    const float4* f4 = (const float4*)f;      // row stride = 128 float4
    float ax = 0.f, ay = 0.f, az = 0.f, aw = 0.f;
    int j = j0 + r;
#pragma unroll 1
    for (; j + 12 < j1; j += 16) {            // 4 independent iterations in flight
        float g0 = g_gw[j];
        float g1 = g_gw[j + 4];
        float g2 = g_gw[j + 8];
        float g3 = g_gw[j + 12];
        float4 v0 = __ldcs(&f4[(size_t)(j     ) * 128 + q]);
        float4 v1 = __ldcs(&f4[(size_t)(j +  4) * 128 + q]);
        float4 v2 = __ldcs(&f4[(size_t)(j +  8) * 128 + q]);
        float4 v3 = __ldcs(&f4[(size_t)(j + 12) * 128 + q]);
        ax += g0 * v0.x + g1 * v1.x + g2 * v2.x + g3 * v3.x;
        ay += g0 * v0.y + g1 * v1.y + g2 * v2.y + g3 * v3.y;
        az += g0 * v0.z + g1 * v1.z + g2 * v2.z + g3 * v3.z;
        aw += g0 * v0.w + g1 * v1.w + g2 * v2.w + g3 * v3.w;
    }
    for (; j < j1; j += 4) {
        float g = g_gw[j];
        float4 v = __ldcs(&f4[(size_t)j * 128 + q]);
        ax += g * v.x; ay += g * v.y; az += g * v.z; aw += g * v.w;
    }
    __shared__ float4 sh[512];
    sh[tid] = make_float4(ax, ay, az, aw);
    __syncthreads();
    if (r == 0) {
        float4 a = sh[q], b = sh[q + 128], c = sh[q + 256], d = sh[q + 384];
        atomicAdd(&out[4 * q + 0], a.x + b.x + c.x + d.x);
        atomicAdd(&out[4 * q + 1], a.y + b.y + c.y + d.y);
        atomicAdd(&out[4 * q + 2], a.z + b.z + c.z + d.z);
        atomicAdd(&out[4 * q + 3], a.w + b.w + c.w + d.w);
    }
}

extern "C" void kernel_launch(void* const* d_in, const int* in_sizes, int n_in,
                              void* d_out, int out_size) {
    const float* features = (const float*)d_in[0];
    const float* attn_w   = (const float*)d_in[1];
    const float* attn_b   = (const float*)d_in[2];
    const int*   kptr     = (const int*)d_in[3];
    float* out = (float*)d_out;

    int d = in_sizes[1];            // 512
    int n = in_sizes[0] / d;        // 100000
    (void)n_in; (void)out_size;

    // K1: dots — 8 warps/block, 1 warp/row
    {
        int rows_per_block = 8;
        int nb = (n + rows_per_block - 1) / rows_per_block;
        k_dot<<<nb, 256>>>(features, attn_w, n);
    }
    // K2: scores + softmax partials
    int nb2 = (n + 255) / 256;
    k_scores<<<nb2, 256>>>(n, kptr, attn_b);
    // K3: fused merge + weights + g + zero bag
    k_weights<<<nb2, 256>>>(out, n, kptr, nb2);
    // K4: weighted column sum (vectorized)
    k_bag<<<592, 512>>>(features, out, n);
}